// round 1
// baseline (speedup 1.0000x reference)
#include <cuda_runtime.h>
#include <math.h>

#define BATCH 4
#define SEQ   4096
#define CH    1024
#define HS    64

// Scratch for projected q, k, v: [B*T, HS] each (4 MB each).
__device__ float g_q[BATCH * SEQ * HS];
__device__ float g_k[BATCH * SEQ * HS];
__device__ float g_v[BATCH * SEQ * HS];

// ---------------------------------------------------------------------------
// Kernel 1: QKV projection.  out[m, n] = sum_k x[m, k] * W[k, n]
// M = B*T = 16384, N = 64, K = 1024.  grid = (M/64, 3), block = 256.
// ---------------------------------------------------------------------------
__global__ __launch_bounds__(256) void qkv_kernel(
    const float* __restrict__ x,
    const float* __restrict__ Wq,
    const float* __restrict__ Wk,
    const float* __restrict__ Wv)
{
    __shared__ __align__(16) float xs[64][33];   // x tile, padded
    __shared__ __align__(16) float ws[32][64];   // W tile

    const float* W  = (blockIdx.y == 0) ? Wq : (blockIdx.y == 1) ? Wk : Wv;
    float*       dst = (blockIdx.y == 0) ? g_q : (blockIdx.y == 1) ? g_k : g_v;

    const int row0 = blockIdx.x * 64;
    const int tid  = threadIdx.x;
    const int tx   = tid & 15;
    const int ty   = tid >> 4;

    float acc[4][4] = {};

    for (int k0 = 0; k0 < CH; k0 += 32) {
        // load x tile: 64 rows x 32 cols = 512 float4
        for (int i = tid; i < 512; i += 256) {
            int r = i >> 3, c4 = i & 7;
            float4 v = *(const float4*)(x + (size_t)(row0 + r) * CH + k0 + c4 * 4);
            xs[r][c4 * 4 + 0] = v.x;
            xs[r][c4 * 4 + 1] = v.y;
            xs[r][c4 * 4 + 2] = v.z;
            xs[r][c4 * 4 + 3] = v.w;
        }
        // load W tile: 32 rows x 64 cols = 512 float4
        for (int i = tid; i < 512; i += 256) {
            int r = i >> 4, c4 = i & 15;
            *(float4*)&ws[r][c4 * 4] =
                *(const float4*)(W + (size_t)(k0 + r) * HS + c4 * 4);
        }
        __syncthreads();

        #pragma unroll
        for (int kk = 0; kk < 32; kk++) {
            float a[4];
            #pragma unroll
            for (int i = 0; i < 4; i++) a[i] = xs[ty * 4 + i][kk];
            float4 bv = *(float4*)&ws[kk][tx * 4];
            #pragma unroll
            for (int i = 0; i < 4; i++) {
                acc[i][0] += a[i] * bv.x;
                acc[i][1] += a[i] * bv.y;
                acc[i][2] += a[i] * bv.z;
                acc[i][3] += a[i] * bv.w;
            }
        }
        __syncthreads();
    }

    #pragma unroll
    for (int i = 0; i < 4; i++) {
        float4 o = make_float4(acc[i][0], acc[i][1], acc[i][2], acc[i][3]);
        *(float4*)(dst + (size_t)(row0 + ty * 4 + i) * HS + tx * 4) = o;
    }
}

// ---------------------------------------------------------------------------
// Kernel 2: causal flash attention, fp32.
// Each block handles TWO query tiles: qb = 63-bx (heavy) then qb = bx,
// so every block processes exactly 65 key tiles -> balanced single wave.
// grid = (32, BATCH), block = 256, dynamic smem = 4 * 64 * 68 * 4 bytes.
// ---------------------------------------------------------------------------
#define PAD 68
#define SMEM_BYTES (4 * 64 * PAD * 4)

__global__ __launch_bounds__(256, 2) void attn_kernel(float* __restrict__ out)
{
    extern __shared__ __align__(16) float smem[];
    float* Qs = smem;
    float* Ks = Qs + 64 * PAD;
    float* Vs = Ks + 64 * PAD;
    float* Ps = Vs + 64 * PAD;

    const int b   = blockIdx.y;
    const int bx  = blockIdx.x;          // 0..31
    const int tid = threadIdx.x;
    const int tx  = tid & 15;
    const int ty  = tid >> 4;

    const float* kg = g_k + (size_t)b * SEQ * HS;
    const float* vg = g_v + (size_t)b * SEQ * HS;

    for (int pass = 0; pass < 2; pass++) {
        const int qb = (pass == 0) ? (63 - bx) : bx;
        const float* qg = g_q + ((size_t)b * SEQ + qb * 64) * HS;

        // load Q tile (64x64) into smem
        for (int i = tid; i < 1024; i += 256) {
            int r = i >> 4, c4 = i & 15;
            *(float4*)&Qs[r * PAD + c4 * 4] =
                *(const float4*)(qg + r * HS + c4 * 4);
        }

        float O[4][4] = {};
        float m[4], l[4];
        #pragma unroll
        for (int i = 0; i < 4; i++) { m[i] = -1e30f; l[i] = 0.f; }

        for (int j0 = 0; j0 <= qb; j0++) {
            // load K, V tiles (64x64 each)
            for (int i = tid; i < 1024; i += 256) {
                int r = i >> 4, c4 = i & 15;
                *(float4*)&Ks[r * PAD + c4 * 4] =
                    *(const float4*)(kg + (size_t)(j0 * 64 + r) * HS + c4 * 4);
                *(float4*)&Vs[r * PAD + c4 * 4] =
                    *(const float4*)(vg + (size_t)(j0 * 64 + r) * HS + c4 * 4);
            }
            __syncthreads();

            // S = Q @ K^T  (thread computes 4x4 tile)
            float S[4][4] = {};
            #pragma unroll 4
            for (int h = 0; h < 64; h += 4) {
                float4 qv[4], kv[4];
                #pragma unroll
                for (int i = 0; i < 4; i++)
                    qv[i] = *(float4*)&Qs[(ty * 4 + i) * PAD + h];
                #pragma unroll
                for (int j = 0; j < 4; j++)
                    kv[j] = *(float4*)&Ks[(tx * 4 + j) * PAD + h];
                #pragma unroll
                for (int i = 0; i < 4; i++)
                    #pragma unroll
                    for (int j = 0; j < 4; j++)
                        S[i][j] += qv[i].x * kv[j].x + qv[i].y * kv[j].y +
                                   qv[i].z * kv[j].z + qv[i].w * kv[j].w;
            }

            const bool diag = (j0 == qb);

            // online softmax per row
            #pragma unroll
            for (int i = 0; i < 4; i++) {
                const int lrow = ty * 4 + i;
                float mloc = -1e30f;
                #pragma unroll
                for (int j = 0; j < 4; j++) {
                    float sv = S[i][j] * 0.125f;          // HS^-0.5
                    if (diag && (tx * 4 + j) > lrow) sv = -1e30f;
                    S[i][j] = sv;
                    mloc = fmaxf(mloc, sv);
                }
                #pragma unroll
                for (int off = 8; off >= 1; off >>= 1)
                    mloc = fmaxf(mloc, __shfl_xor_sync(0xffffffffu, mloc, off));

                float mnew  = fmaxf(m[i], mloc);
                float alpha = __expf(m[i] - mnew);
                float rsum  = 0.f;
                #pragma unroll
                for (int j = 0; j < 4; j++) {
                    float p = __expf(S[i][j] - mnew);
                    S[i][j] = p;
                    rsum += p;
                }
                #pragma unroll
                for (int off = 8; off >= 1; off >>= 1)
                    rsum += __shfl_xor_sync(0xffffffffu, rsum, off);

                l[i] = l[i] * alpha + rsum;
                m[i] = mnew;
                #pragma unroll
                for (int j = 0; j < 4; j++) O[i][j] *= alpha;
            }

            // write P to smem for the PV gemm
            #pragma unroll
            for (int i = 0; i < 4; i++)
                *(float4*)&Ps[(ty * 4 + i) * PAD + tx * 4] =
                    make_float4(S[i][0], S[i][1], S[i][2], S[i][3]);
            __syncthreads();

            // O += P @ V
            #pragma unroll 4
            for (int kk = 0; kk < 64; kk += 4) {
                float4 pv[4], vv[4];
                #pragma unroll
                for (int i = 0; i < 4; i++)
                    pv[i] = *(float4*)&Ps[(ty * 4 + i) * PAD + kk];
                #pragma unroll
                for (int c = 0; c < 4; c++)
                    vv[c] = *(float4*)&Vs[(kk + c) * PAD + tx * 4];
                #pragma unroll
                for (int i = 0; i < 4; i++) {
                    O[i][0] += pv[i].x * vv[0].x + pv[i].y * vv[1].x +
                               pv[i].z * vv[2].x + pv[i].w * vv[3].x;
                    O[i][1] += pv[i].x * vv[0].y + pv[i].y * vv[1].y +
                               pv[i].z * vv[2].y + pv[i].w * vv[3].y;
                    O[i][2] += pv[i].x * vv[0].z + pv[i].y * vv[1].z +
                               pv[i].z * vv[2].z + pv[i].w * vv[3].z;
                    O[i][3] += pv[i].x * vv[0].w + pv[i].y * vv[1].w +
                               pv[i].z * vv[2].w + pv[i].w * vv[3].w;
                }
            }
            __syncthreads();
        }

        // epilogue: normalize and write out
        #pragma unroll
        for (int i = 0; i < 4; i++) {
            float inv = 1.0f / l[i];
            float4 o = make_float4(O[i][0] * inv, O[i][1] * inv,
                                   O[i][2] * inv, O[i][3] * inv);
            *(float4*)(out + ((size_t)b * SEQ + qb * 64 + ty * 4 + i) * HS +
                       tx * 4) = o;
        }
        // smem reuse across passes is protected by the loop-end __syncthreads()
    }
}

// ---------------------------------------------------------------------------
extern "C" void kernel_launch(void* const* d_in, const int* in_sizes, int n_in,
                              void* d_out, int out_size)
{
    const float* x  = (const float*)d_in[0];
    const float* Wq = (const float*)d_in[1];
    const float* Wk = (const float*)d_in[2];
    const float* Wv = (const float*)d_in[3];
    float* out = (float*)d_out;

    cudaFuncSetAttribute(attn_kernel,
                         cudaFuncAttributeMaxDynamicSharedMemorySize,
                         SMEM_BYTES);

    // QKV projection: grid (M/64, 3)
    qkv_kernel<<<dim3(BATCH * SEQ / 64, 3), 256>>>(x, Wq, Wk, Wv);

    // Flash attention: 32 paired query-tile blocks per batch (balanced wave)
    attn_kernel<<<dim3(32, BATCH), 256, SMEM_BYTES>>>(out);
}